// round 2
// baseline (speedup 1.0000x reference)
#include <cuda_runtime.h>
#include <math.h>
#include <stddef.h>

// Problem constants
#define B_  2
#define S_  2048
#define D_  1024
#define H_  16
#define FK_ 32
#define DK_ 64
#define BH_ (B_*H_)

typedef unsigned long long u64;

// ---------------- packed f32x2 helpers (sm_103a FFMA2 path) ----------------
__device__ __forceinline__ u64 pack_dup(float x) {
    u64 r; asm("mov.b64 %0, {%1, %1};" : "=l"(r) : "f"(x)); return r;
}
__device__ __forceinline__ void ffma2(u64& d, u64 a, u64 b) {
    asm("fma.rn.f32x2 %0, %1, %2, %3;" : "=l"(d) : "l"(a), "l"(b), "l"(d));
}
__device__ __forceinline__ void unpack2(u64 a, float& x, float& y) {
    asm("mov.b64 {%0, %1}, %2;" : "=f"(x), "=f"(y) : "l"(a));
}

// ---------------- scratch (__device__ globals; no allocation allowed) ----------------
__device__ float g_M[H_*DK_*DK_];                 // per-head collapsed 64x64 projection
__device__ float g_Qp[B_*S_*D_];                  // [B,S,D] layout (h*64+d)
__device__ float g_vp[B_*S_*D_];                  // v@Wv+bv, [B,S,D]
__device__ float g_concat[B_*S_*D_];              // attention output pre-Wo
__device__ float g_scores[134217728];             // [B*H, S, S] = 512 MB

// ---------------- 1) collapse the low-rank chain per head, in fp64 ----------------
__global__ void compute_M_kernel(const float* __restrict__ W_A,
                                 const float* __restrict__ W_A2) {
    int h = blockIdx.x;
    __shared__ double T1[64*64];   // Wa@Wb
    __shared__ double T2[64*32];   // T1@Wa2
    const float* WAh  = W_A  + h*2048;
    const float* WA2h = W_A2 + h*2048;

    for (int idx = threadIdx.x; idx < 4096; idx += blockDim.x) {
        int c = idx >> 6, d = idx & 63;
        double acc = 0.0;
        #pragma unroll 8
        for (int j = 0; j < 32; j++)
            acc += (double)WAh[c*32 + j] * (double)WAh[j*64 + d];
        T1[idx] = acc;
    }
    __syncthreads();
    for (int idx = threadIdx.x; idx < 2048; idx += blockDim.x) {
        int c = idx >> 5, j = idx & 31;
        double acc = 0.0;
        #pragma unroll 8
        for (int d = 0; d < 64; d++)
            acc += T1[c*64 + d] * (double)WA2h[d*32 + j];
        T2[idx] = acc;
    }
    __syncthreads();
    for (int idx = threadIdx.x; idx < 4096; idx += blockDim.x) {
        int c = idx >> 6, d = idx & 63;
        double acc = 0.0;
        #pragma unroll 8
        for (int j = 0; j < 32; j++)
            acc += T2[c*32 + j] * (double)WA2h[j*64 + d];
        g_M[h*4096 + idx] = (float)acc;
    }
}

// ---------------- 2) Qp = q @ M[h] per head ----------------
__global__ void qp_kernel(const float* __restrict__ q) {
    int token = blockIdx.x;
    __shared__ float qs[D_];
    const float* qrow = q + (size_t)token * D_;
    for (int i = threadIdx.x; i < D_; i += 256) qs[i] = qrow[i];
    __syncthreads();
    int d  = threadIdx.x & 63;
    int h0 = threadIdx.x >> 6;          // 0..3
    float* out = g_Qp + (size_t)token * D_;
    #pragma unroll
    for (int hh = 0; hh < 4; hh++) {
        int h = h0 * 4 + hh;
        const float* Mh = g_M + h*4096;
        const float* qh = qs + h*64;
        float acc = 0.f;
        #pragma unroll 8
        for (int c = 0; c < 64; c++) acc = fmaf(qh[c], Mh[c*64 + d], acc);
        out[h*64 + d] = acc;
    }
}

// ---------------- 3) SGEMM with FFMA2: C = A[M,K] @ B[K,N] + bias ----------------
// 128x128 tile, BK=16, 256 threads, 8x8 micro-tile (acc packed pairwise over j).
// A tile is stored in shared PRE-DUPLICATED as {x,x} u64 so the inner loop has
// zero packing movs: 6x LDS.128 + 32x FFMA2 per k-step.
__global__ __launch_bounds__(256)
void sgemm_nn_bias(int M, int N, int K,
                   const float* __restrict__ A,
                   const float* __restrict__ Bm,
                   const float* __restrict__ bias,
                   float* __restrict__ C) {
    __shared__ u64   As2[16][128];   // 16 KB, dup-packed A^T tile
    __shared__ float Bs[16][128];    // 8 KB
    int bm = blockIdx.y * 128;
    int bn = blockIdx.x * 128;
    int tid = threadIdx.x;
    int tx = tid & 15, ty = tid >> 4;

    u64 acc[8][4];
    #pragma unroll
    for (int i = 0; i < 8; i++)
        #pragma unroll
        for (int p = 0; p < 4; p++) acc[i][p] = 0ull;

    int arow = tid >> 1;          // 0..127
    int acol = (tid & 1) * 8;     // 0 or 8
    int brow = tid >> 4;          // 0..15
    int bcol = (tid & 15) * 8;    // 0..120

    for (int k0 = 0; k0 < K; k0 += 16) {
        const float* Ap = A + (size_t)(bm + arow) * K + k0 + acol;
        float4 a0 = *(const float4*)Ap;
        float4 a1 = *(const float4*)(Ap + 4);
        As2[acol+0][arow] = pack_dup(a0.x); As2[acol+1][arow] = pack_dup(a0.y);
        As2[acol+2][arow] = pack_dup(a0.z); As2[acol+3][arow] = pack_dup(a0.w);
        As2[acol+4][arow] = pack_dup(a1.x); As2[acol+5][arow] = pack_dup(a1.y);
        As2[acol+6][arow] = pack_dup(a1.z); As2[acol+7][arow] = pack_dup(a1.w);

        const float* Bp = Bm + (size_t)(k0 + brow) * N + bn + bcol;
        *(float4*)&Bs[brow][bcol]     = *(const float4*)Bp;
        *(float4*)&Bs[brow][bcol + 4] = *(const float4*)(Bp + 4);
        __syncthreads();

        #pragma unroll
        for (int kk = 0; kk < 16; kk++) {
            const ulonglong2* ap = (const ulonglong2*)&As2[kk][ty*8];
            ulonglong2 a01 = ap[0], a23 = ap[1], a45 = ap[2], a67 = ap[3];
            const ulonglong2* bp = (const ulonglong2*)&Bs[kk][tx*8];
            ulonglong2 b01 = bp[0], b23 = bp[1];
            u64 av[8] = {a01.x, a01.y, a23.x, a23.y, a45.x, a45.y, a67.x, a67.y};
            u64 bv[4] = {b01.x, b01.y, b23.x, b23.y};
            #pragma unroll
            for (int i = 0; i < 8; i++)
                #pragma unroll
                for (int p = 0; p < 4; p++)
                    ffma2(acc[i][p], av[i], bv[p]);
        }
        __syncthreads();
    }

    #pragma unroll
    for (int i = 0; i < 8; i++) {
        int row = bm + ty*8 + i;
        float* Cp = C + (size_t)row * N + bn + tx*8;
        float o[8];
        #pragma unroll
        for (int p = 0; p < 4; p++) {
            float lo, hi; unpack2(acc[i][p], lo, hi);
            o[2*p]   = lo + bias[bn + tx*8 + 2*p];
            o[2*p+1] = hi + bias[bn + tx*8 + 2*p+1];
        }
        *(float4*)(Cp)     = *(float4*)(o);
        *(float4*)(Cp + 4) = *(float4*)(o + 4);
    }
}

// ---------------- 4) batched NT GEMM with FFMA2: scores = Qp . q^T per head ----
// K = 64. grid (S/128, S/128, B*H)
__global__ __launch_bounds__(256)
void scores_kernel(const float* __restrict__ q) {
    int bh = blockIdx.z;
    int b = bh >> 4, h = bh & 15;
    const float* A  = g_Qp + (size_t)b * S_ * D_ + h * 64;   // row stride D_
    const float* Bt = q    + (size_t)b * S_ * D_ + h * 64;   // row stride D_
    float* C = g_scores + (size_t)bh * S_ * S_;

    __shared__ u64   As2[16][128];   // dup-packed
    __shared__ float Bs[16][128];
    int bm = blockIdx.y * 128;
    int bn = blockIdx.x * 128;
    int tid = threadIdx.x;
    int tx = tid & 15, ty = tid >> 4;

    u64 acc[8][4];
    #pragma unroll
    for (int i = 0; i < 8; i++)
        #pragma unroll
        for (int p = 0; p < 4; p++) acc[i][p] = 0ull;

    int arow = tid >> 1;
    int acol = (tid & 1) * 8;

    for (int k0 = 0; k0 < 64; k0 += 16) {
        const float* Ap = A + (size_t)(bm + arow) * D_ + k0 + acol;
        float4 a0 = *(const float4*)Ap;
        float4 a1 = *(const float4*)(Ap + 4);
        As2[acol+0][arow] = pack_dup(a0.x); As2[acol+1][arow] = pack_dup(a0.y);
        As2[acol+2][arow] = pack_dup(a0.z); As2[acol+3][arow] = pack_dup(a0.w);
        As2[acol+4][arow] = pack_dup(a1.x); As2[acol+5][arow] = pack_dup(a1.y);
        As2[acol+6][arow] = pack_dup(a1.z); As2[acol+7][arow] = pack_dup(a1.w);

        const float* Bp = Bt + (size_t)(bn + arow) * D_ + k0 + acol;
        float4 b0 = *(const float4*)Bp;
        float4 b1 = *(const float4*)(Bp + 4);
        Bs[acol+0][arow] = b0.x; Bs[acol+1][arow] = b0.y;
        Bs[acol+2][arow] = b0.z; Bs[acol+3][arow] = b0.w;
        Bs[acol+4][arow] = b1.x; Bs[acol+5][arow] = b1.y;
        Bs[acol+6][arow] = b1.z; Bs[acol+7][arow] = b1.w;
        __syncthreads();

        #pragma unroll
        for (int kk = 0; kk < 16; kk++) {
            const ulonglong2* ap = (const ulonglong2*)&As2[kk][ty*8];
            ulonglong2 a01 = ap[0], a23 = ap[1], a45 = ap[2], a67 = ap[3];
            const ulonglong2* bp = (const ulonglong2*)&Bs[kk][tx*8];
            ulonglong2 b01 = bp[0], b23 = bp[1];
            u64 av[8] = {a01.x, a01.y, a23.x, a23.y, a45.x, a45.y, a67.x, a67.y};
            u64 bv[4] = {b01.x, b01.y, b23.x, b23.y};
            #pragma unroll
            for (int i = 0; i < 8; i++)
                #pragma unroll
                for (int p = 0; p < 4; p++)
                    ffma2(acc[i][p], av[i], bv[p]);
        }
        __syncthreads();
    }

    #pragma unroll
    for (int i = 0; i < 8; i++) {
        int row = bm + ty*8 + i;
        float* Cp = C + (size_t)row * S_ + bn + tx*8;
        float o[8];
        #pragma unroll
        for (int p = 0; p < 4; p++) {
            float lo, hi; unpack2(acc[i][p], lo, hi);
            o[2*p] = lo; o[2*p+1] = hi;
        }
        *(float4*)(Cp)     = *(float4*)(o);
        *(float4*)(Cp + 4) = *(float4*)(o + 4);
    }
}

// ---------------- 5) softmax + sparse PV gather (deterministic, warp-shuffle) ----
// scores are ~1e5 scale -> softmax is (near) one-hot. exp(x-m) underflows to 0
// for x-m < -104 in fp32 (reference underflows identically), so only terms with
// s > max-104 contribute. Compact them in t-order via prefix scan (no atomics).
__global__ __launch_bounds__(256)
void softmax_pv_kernel() {
    int s  = blockIdx.x;
    int bh = blockIdx.y;
    int b = bh >> 4, h = bh & 15;
    const float* row = g_scores + ((size_t)bh * S_ + s) * S_;

    __shared__ float warp_max[8];
    __shared__ int   warp_tot[8];
    __shared__ int   tlist[S_];
    __shared__ float wlist[S_];

    int tid = threadIdx.x;
    int lane = tid & 31, w = tid >> 5;

    // thread owns contiguous t chunk [tid*8, tid*8+8)
    float v8[8];
    {
        const float4* rp = (const float4*)(row + tid * 8);
        float4 r0 = rp[0], r1 = rp[1];
        v8[0]=r0.x; v8[1]=r0.y; v8[2]=r0.z; v8[3]=r0.w;
        v8[4]=r1.x; v8[5]=r1.y; v8[6]=r1.z; v8[7]=r1.w;
    }
    float m = v8[0];
    #pragma unroll
    for (int i = 1; i < 8; i++) m = fmaxf(m, v8[i]);
    #pragma unroll
    for (int off = 16; off > 0; off >>= 1)
        m = fmaxf(m, __shfl_xor_sync(0xFFFFFFFFu, m, off));
    if (lane == 0) warp_max[w] = m;
    __syncthreads();
    m = warp_max[0];
    #pragma unroll
    for (int i = 1; i < 8; i++) m = fmaxf(m, warp_max[i]);

    // count actives
    int c = 0;
    #pragma unroll
    for (int i = 0; i < 8; i++) c += (v8[i] - m > -104.0f) ? 1 : 0;

    // warp inclusive scan + cross-warp base (deterministic)
    int sc = c;
    #pragma unroll
    for (int off = 1; off < 32; off <<= 1) {
        int y = __shfl_up_sync(0xFFFFFFFFu, sc, off);
        if (lane >= off) sc += y;
    }
    if (lane == 31) warp_tot[w] = sc;
    __syncthreads();
    int base = 0, L = 0;
    #pragma unroll
    for (int i = 0; i < 8; i++) {
        if (i < w) base += warp_tot[i];
        L += warp_tot[i];
    }
    int p = base + sc - c;   // exclusive prefix for this thread
    #pragma unroll
    for (int i = 0; i < 8; i++) {
        float dsc = v8[i] - m;
        if (dsc > -104.0f) {
            tlist[p] = tid * 8 + i;
            wlist[p] = expf(dsc);
            p++;
        }
    }
    __syncthreads();

    // denominator: serial over L (L is typically 1-4), identical fixed order
    float denom = 0.f;
    for (int i = 0; i < L; i++) denom += wlist[i];

    // weighted gather of vp rows
    if (tid < 64) {
        float o = 0.f;
        const float* vpb = g_vp + (size_t)b * S_ * D_ + h * 64 + tid;
        for (int i = 0; i < L; i++)
            o = fmaf(wlist[i], vpb[(size_t)tlist[i] * D_], o);
        g_concat[((size_t)b * S_ + s) * D_ + h * 64 + tid] = o / denom;
    }
}

// ---------------- launcher ----------------
extern "C" void kernel_launch(void* const* d_in, const int* in_sizes, int n_in,
                              void* d_out, int out_size) {
    const float* q    = (const float*)d_in[0];
    // d_in[1] = k  (unused in the reference forward)
    const float* v    = (const float*)d_in[2];
    const float* Wv   = (const float*)d_in[3];
    const float* bv   = (const float*)d_in[4];
    const float* W_A  = (const float*)d_in[5];
    const float* W_A2 = (const float*)d_in[6];
    const float* Wo   = (const float*)d_in[7];
    const float* bo   = (const float*)d_in[8];
    float* out = (float*)d_out;

    float* vp;     cudaGetSymbolAddress((void**)&vp,     g_vp);
    float* concat; cudaGetSymbolAddress((void**)&concat, g_concat);

    compute_M_kernel<<<H_, 256>>>(W_A, W_A2);
    qp_kernel<<<B_*S_, 256>>>(q);
    sgemm_nn_bias<<<dim3(D_/128, (B_*S_)/128), 256>>>(B_*S_, D_, D_, v, Wv, bv, vp);
    scores_kernel<<<dim3(S_/128, S_/128, BH_), 256>>>(q);
    softmax_pv_kernel<<<dim3(S_, BH_), 256>>>();
    sgemm_nn_bias<<<dim3(D_/128, (B_*S_)/128), 256>>>(B_*S_, D_, D_, concat, Wo, bo, out);
}